// round 9
// baseline (speedup 1.0000x reference)
#include <cuda_runtime.h>
#include <cstdint>

#define NPTS     16384
#define NB       256
#define XMIN     (-4.0f)
#define BW       0.03125f           // 8/256, exact in binary
#define INVBW    32.0f
#define HBLOCKS  64                 // hist/scatter blocks (32 per set)
#define HTHREADS 256
#define PPB      512                // points per hist/scatter block
#define MTHREADS 128                // 4 independent warps per block
#define MBLOCKS  256                // 1024 warps total: 512 per direction
#define HOMEW    256                // initial window (ranks)
#define STEP     128                // expansion step (ranks)
#define FTHREADS 1024
#define NWARPS   (MBLOCKS * MTHREADS / 32)

#define POS_INF __int_as_float(0x7f800000)

// ---------------- persistent scratch (rewritten every call) ----------------
__device__ int    g_part[HBLOCKS][NB];     // per-block partial histograms
__device__ int    g_boff[2][NB + 1];       // bucket start offsets
__device__ int    g_cur[2][NB];            // scatter cursors
__device__ float4 g_sorted[2][NPTS];       // (x,y,z,|p|^2), bucket-sorted by x
__device__ float  g_wsum[NWARPS];          // per-warp distance sums

__device__ __forceinline__ int bucket_of(float x) {
    int b = (int)floorf((x - XMIN) * INVBW);
    return min(max(b, 0), NB - 1);
}
// unseen-left points (rank < lo) are in buckets <= bucket_of(B[lo].x): x < right edge
__device__ __forceinline__ float right_edge(int b) {
    return (b >= NB - 1) ? 1e30f : (XMIN + (float)(b + 1) * BW);
}
// unseen-right points (rank >= hi) are in buckets >= bucket_of(B[hi-1].x): x >= left edge
__device__ __forceinline__ float left_edge(int b) {
    return (b <= 0) ? -1e30f : (XMIN + (float)b * BW);
}

// ---------------- kernel 1: partial histograms (64 blocks) ----------------
__global__ void __launch_bounds__(HTHREADS)
hist_kernel(const float* __restrict__ pred, const float* __restrict__ targ) {
    __shared__ int h[NB];
    const int set   = blockIdx.x >> 5;
    const int slice = blockIdx.x & 31;
    const float* __restrict__ src = set ? targ : pred;
    const int tid = threadIdx.x;

    h[tid] = 0;
    __syncthreads();
#pragma unroll
    for (int r = 0; r < PPB / HTHREADS; r++) {
        const int i = slice * PPB + r * HTHREADS + tid;
        atomicAdd(&h[bucket_of(src[3 * i])], 1);
    }
    __syncthreads();
    g_part[blockIdx.x][tid] = h[tid];
}

// ---------------- kernel 2: sum partials + prefix scan (1 block) ----------
__global__ void __launch_bounds__(2 * NB)
scan_kernel() {
    __shared__ int sVal[2 * NB];
    const int tid = threadIdx.x;
    const int set = tid >> 8;
    const int b   = tid & (NB - 1);

    int cnt = 0;
#pragma unroll 8
    for (int k = 0; k < 32; k++) cnt += g_part[set * 32 + k][b];

    sVal[tid] = cnt;
    __syncthreads();
    for (int st = 1; st < NB; st <<= 1) {
        int add = (b >= st) ? sVal[tid - st] : 0;
        __syncthreads();
        sVal[tid] += add;
        __syncthreads();
    }
    const int excl = sVal[tid] - cnt;
    g_boff[set][b] = excl;
    g_cur[set][b]  = excl;
    if (b == NB - 1) g_boff[set][NB] = sVal[tid];
}

// ---------------- kernel 3: scatter into bucket-sorted order --------------
__global__ void __launch_bounds__(HTHREADS)
scatter_kernel(const float* __restrict__ pred, const float* __restrict__ targ) {
    const int set   = blockIdx.x >> 5;
    const int slice = blockIdx.x & 31;
    const float* __restrict__ src = set ? targ : pred;
    const int tid = threadIdx.x;

#pragma unroll
    for (int r = 0; r < PPB / HTHREADS; r++) {
        const int i = slice * PPB + r * HTHREADS + tid;
        float x = src[3 * i + 0];
        float y = src[3 * i + 1];
        float z = src[3 * i + 2];
        int pos = atomicAdd(&g_cur[set][bucket_of(x)], 1);
        g_sorted[set][pos] = make_float4(x, y, z, x * x + y * y + z * z);
    }
}

// ---------------- kernel 4: warp-autonomous windowed NN -------------------
// Each warp owns 32 consecutive sorted queries (one per lane) and scans a
// contiguous rank-window of the opposite sorted array straight from gmem:
// identical addresses across lanes (broadcast), independent candidates
// (unroll -> MLP~8), zero block syncs. Ballot-voted ring expansion with
// bucket-edge lower bounds.
__global__ void __launch_bounds__(MTHREADS)
main_kernel() {
    const int wglobal = (blockIdx.x * MTHREADS + threadIdx.x) >> 5;
    const int lane    = threadIdx.x & 31;
    const int dir     = wglobal >> 9;             // 512 warps per direction
    const int wq      = wglobal & 511;
    const int aset    = dir, bset = 1 - dir;
    const int q       = wq * 32 + lane;

    const float4 a = g_sorted[aset][q];
    const float amx = -2.0f * a.x;
    const float amy = -2.0f * a.y;
    const float amz = -2.0f * a.z;
    const float ca  = a.w;

    const float4* __restrict__ B = g_sorted[bset];

    float best = POS_INF;

    // scan a contiguous rank range [s, e), e-s multiple of 4
    auto scan = [&](int s, int e) {
#pragma unroll 2
        for (int j = s; j < e; j += 4) {
            float4 b0 = B[j + 0];
            float4 b1 = B[j + 1];
            float4 b2 = B[j + 2];
            float4 b3 = B[j + 3];
            float s0 = fmaf(amx, b0.x, fmaf(amy, b0.y, fmaf(amz, b0.z, b0.w)));
            float s1 = fmaf(amx, b1.x, fmaf(amy, b1.y, fmaf(amz, b1.z, b1.w)));
            float s2 = fmaf(amx, b2.x, fmaf(amy, b2.y, fmaf(amz, b2.z, b2.w)));
            float s3 = fmaf(amx, b3.x, fmaf(amy, b3.y, fmaf(amz, b3.z, b3.w)));
            best = fminf(best, fminf(fminf(s0, s1), fminf(s2, s3)));
        }
    };

    // home window centered at the matching rank
    int lo = wq * 32 + 16 - HOMEW / 2;
    lo = min(max(lo, 0), NPTS - HOMEW);
    int hi = lo + HOMEW;
    scan(lo, hi);

    float eL = right_edge(bucket_of(B[lo].x));
    float eR = left_edge(bucket_of(B[hi - 1].x));

    for (;;) {
        const float bound = fmaxf(ca + best, 0.0f);  // current best d^2
        const float dxl = fmaxf(a.x - eL, 0.0f);
        const float dxr = fmaxf(eR - a.x, 0.0f);
        const bool needL = (lo > 0)    && (dxl * dxl < bound);
        const bool needR = (hi < NPTS) && (dxr * dxr < bound);
        const unsigned mL = __ballot_sync(0xFFFFFFFFu, needL);
        const unsigned mR = __ballot_sync(0xFFFFFFFFu, needR);
        if (!(mL | mR)) break;
        if (mL) {
            const int nlo = max(lo - STEP, 0);
            scan(nlo, lo);
            lo = nlo;
            eL = right_edge(bucket_of(B[lo].x));
        }
        if (mR) {
            const int nhi = min(hi + STEP, NPTS);
            scan(hi, nhi);
            hi = nhi;
            eR = left_edge(bucket_of(B[hi - 1].x));
        }
    }

    float d = sqrtf(fmaxf(ca + best, 0.0f));
#pragma unroll
    for (int s = 16; s > 0; s >>= 1)
        d += __shfl_xor_sync(0xFFFFFFFFu, d, s);
    if (lane == 0) g_wsum[wglobal] = d;
}

// ---------------- kernel 5: final sum over 1024 warp partials -------------
__global__ void __launch_bounds__(FTHREADS)
final_kernel(float* __restrict__ out) {
    float v = g_wsum[threadIdx.x];
#pragma unroll
    for (int s = 16; s > 0; s >>= 1)
        v += __shfl_xor_sync(0xFFFFFFFFu, v, s);
    __shared__ float sRed[FTHREADS / 32];
    if ((threadIdx.x & 31) == 0) sRed[threadIdx.x >> 5] = v;
    __syncthreads();
    if (threadIdx.x == 0) {
        float t = 0.0f;
#pragma unroll
        for (int w = 0; w < FTHREADS / 32; w++) t += sRed[w];
        out[0] = t * (1.0f / (float)NPTS);
    }
}

// ---------------- launch ----------------
extern "C" void kernel_launch(void* const* d_in, const int* in_sizes, int n_in,
                              void* d_out, int out_size) {
    const float* pred = (const float*)d_in[0];
    const float* targ = (const float*)d_in[1];
    float* out = (float*)d_out;

    hist_kernel<<<HBLOCKS, HTHREADS>>>(pred, targ);
    scan_kernel<<<1, 2 * NB>>>();
    scatter_kernel<<<HBLOCKS, HTHREADS>>>(pred, targ);
    main_kernel<<<MBLOCKS, MTHREADS>>>();
    final_kernel<<<1, FTHREADS>>>(out);
}

// round 10
// speedup vs baseline: 10.0651x; 10.0651x over previous
#include <cuda_runtime.h>
#include <cstdint>

#define NPTS     16384
#define NB       256
#define XMIN     (-4.0f)
#define BW       0.03125f           // 8/256, exact in binary
#define INVBW    32.0f
#define HBLOCKS  64                 // hist/scatter blocks (32 per set)
#define HTHREADS 256
#define PPB      512                // points per hist/scatter block
#define GSIZE    64                 // queries per group
#define NGRP     512                // 256 per direction
#define NTILE    8                  // window tiles per group
#define TILE     256                // ranks per tile  (window = 2048 ranks)
#define WHALF    1024
#define RBLOCKS  128
#define RTHREADS 256
#define FBBLOCKS 256
#define FBTHREADS 256

#define POS_INF __int_as_float(0x7f800000)

// ---------------- persistent scratch (rewritten every call) ----------------
__device__ int    g_part[HBLOCKS][NB];       // per-block partial histograms
__device__ int    g_boff[2][NB + 1];         // bucket start offsets
__device__ int    g_cur[2][NB];              // scatter cursors
__device__ float4 g_sorted[2][NPTS];         // (x,y,z,|p|^2), bucket-sorted by x
__device__ float  g_tmin[2 * NPTS][NTILE];   // per-(query,tile) partial mins (1 MB)
__device__ float  g_partial[RBLOCKS];        // resolve-block sums
__device__ int    g_unres[2 * NPTS];         // unresolved query list
__device__ int    g_ucnt;                    // list count
__device__ float  g_fsum;                    // fallback sum

__device__ __forceinline__ int bucket_of(float x) {
    int b = (int)floorf((x - XMIN) * INVBW);
    return min(max(b, 0), NB - 1);
}
// unseen-left points (rank < lo) lie in buckets <= bucket_of(B[lo].x): x < right edge
__device__ __forceinline__ float right_edge(int b) {
    return (b >= NB - 1) ? 1e30f : (XMIN + (float)(b + 1) * BW);
}
// unseen-right points (rank >= hi) lie in buckets >= bucket_of(B[hi-1].x): x >= left edge
__device__ __forceinline__ float left_edge(int b) {
    return (b <= 0) ? -1e30f : (XMIN + (float)b * BW);
}

// ---------------- packed f32x2 helpers ----------------
__device__ __forceinline__ unsigned long long pack2(float lo, float hi) {
    unsigned long long r;
    asm("mov.b64 %0, {%1, %2};" : "=l"(r) : "f"(lo), "f"(hi));
    return r;
}
__device__ __forceinline__ unsigned long long fma2(unsigned long long a,
                                                   unsigned long long b,
                                                   unsigned long long c) {
    unsigned long long d;
    asm("fma.rn.f32x2 %0, %1, %2, %3;" : "=l"(d) : "l"(a), "l"(b), "l"(c));
    return d;
}
__device__ __forceinline__ void unpack2(unsigned long long v, float& lo, float& hi) {
    asm("mov.b64 {%0, %1}, %2;" : "=f"(lo), "=f"(hi) : "l"(v));
}

__device__ __forceinline__ int window_base(int grp_local) {
    int c = grp_local * GSIZE + GSIZE / 2;
    int b = c - WHALF;
    return min(max(b, 0), NPTS - NTILE * TILE);
}

// ---------------- kernel 1: partial histograms ----------------
__global__ void __launch_bounds__(HTHREADS)
hist_kernel(const float* __restrict__ pred, const float* __restrict__ targ) {
    __shared__ int h[NB];
    const int set   = blockIdx.x >> 5;
    const int slice = blockIdx.x & 31;
    const float* __restrict__ src = set ? targ : pred;
    const int tid = threadIdx.x;
    h[tid] = 0;
    __syncthreads();
#pragma unroll
    for (int r = 0; r < PPB / HTHREADS; r++) {
        const int i = slice * PPB + r * HTHREADS + tid;
        atomicAdd(&h[bucket_of(src[3 * i])], 1);
    }
    __syncthreads();
    g_part[blockIdx.x][tid] = h[tid];
}

// ---------------- kernel 2: prefix scan + state reset ----------------
__global__ void __launch_bounds__(2 * NB)
scan_kernel() {
    __shared__ int sVal[2 * NB];
    const int tid = threadIdx.x;
    const int set = tid >> 8;
    const int b   = tid & (NB - 1);
    if (tid == 0) { g_ucnt = 0; g_fsum = 0.0f; }

    int cnt = 0;
#pragma unroll 8
    for (int k = 0; k < 32; k++) cnt += g_part[set * 32 + k][b];
    sVal[tid] = cnt;
    __syncthreads();
    for (int st = 1; st < NB; st <<= 1) {
        int add = (b >= st) ? sVal[tid - st] : 0;
        __syncthreads();
        sVal[tid] += add;
        __syncthreads();
    }
    const int excl = sVal[tid] - cnt;
    g_boff[set][b] = excl;
    g_cur[set][b]  = excl;
    if (b == NB - 1) g_boff[set][NB] = sVal[tid];
}

// ---------------- kernel 3: scatter into bucket-sorted order --------------
__global__ void __launch_bounds__(HTHREADS)
scatter_kernel(const float* __restrict__ pred, const float* __restrict__ targ) {
    const int set   = blockIdx.x >> 5;
    const int slice = blockIdx.x & 31;
    const float* __restrict__ src = set ? targ : pred;
    const int tid = threadIdx.x;
#pragma unroll
    for (int r = 0; r < PPB / HTHREADS; r++) {
        const int i = slice * PPB + r * HTHREADS + tid;
        float x = src[3 * i + 0];
        float y = src[3 * i + 1];
        float z = src[3 * i + 2];
        int pos = atomicAdd(&g_cur[set][bucket_of(x)], 1);
        g_sorted[set][pos] = make_float4(x, y, z, x * x + y * y + z * z);
    }
}

// ---------------- kernel 4: phase A — flat windowed tile scan -------------
// 4096 CTAs of 64 threads: block = (group, tile). One query per thread,
// 256-rank tile staged to smem, packed f32x2 scan, partial min to g_tmin.
// No votes, no expansion: pure flat parallel work.
__global__ void __launch_bounds__(GSIZE)
phasea_kernel() {
    __shared__ __align__(16) float sx[TILE], sy[TILE], sz[TILE], sc[TILE];

    const int grp  = blockIdx.x >> 3;          // 0..511
    const int tile = blockIdx.x & 7;
    const int dir  = grp >> 8;
    const int grpl = grp & 255;
    const int aset = dir, bset = 1 - dir;
    const int tid  = threadIdx.x;
    const int q    = grpl * GSIZE + tid;       // local query rank

    const int t0 = window_base(grpl) + tile * TILE;
    const float4* __restrict__ B = g_sorted[bset];

    // stage tile (SoA)
#pragma unroll
    for (int r = 0; r < TILE / GSIZE; r++) {
        const int s = tid + r * GSIZE;         // coalesced across threads
        float4 v = B[t0 + s];
        sx[s] = v.x; sy[s] = v.y; sz[s] = v.z; sc[s] = v.w;
    }

    const float4 a = g_sorted[aset][q];
    const unsigned long long ax2 = pack2(-2.0f * a.x, -2.0f * a.x);
    const unsigned long long ay2 = pack2(-2.0f * a.y, -2.0f * a.y);
    const unsigned long long az2 = pack2(-2.0f * a.z, -2.0f * a.z);
    __syncthreads();

    float mlo = POS_INF, mhi = POS_INF;
#pragma unroll 8
    for (int j = 0; j < TILE; j += 4) {
        ulonglong2 vx = *(const ulonglong2*)&sx[j];
        ulonglong2 vy = *(const ulonglong2*)&sy[j];
        ulonglong2 vz = *(const ulonglong2*)&sz[j];
        ulonglong2 vc = *(const ulonglong2*)&sc[j];
        unsigned long long s01 = fma2(ax2, vx.x, fma2(ay2, vy.x, fma2(az2, vz.x, vc.x)));
        unsigned long long s23 = fma2(ax2, vx.y, fma2(ay2, vy.y, fma2(az2, vz.y, vc.y)));
        float s0, s1, s2, s3;
        unpack2(s01, s0, s1);
        unpack2(s23, s2, s3);
        mlo = fminf(mlo, fminf(s0, s2));
        mhi = fminf(mhi, fminf(s1, s3));
    }
    g_tmin[dir * NPTS + q][tile] = fminf(mlo, mhi);
}

// ---------------- kernel 5: resolve — reduce tiles, bound check -----------
__global__ void __launch_bounds__(RTHREADS)
resolve_kernel() {
    const int gq   = blockIdx.x * RTHREADS + threadIdx.x;  // 0..32767
    const int dir  = gq >> 14;
    const int q    = gq & (NPTS - 1);
    const int aset = dir, bset = 1 - dir;

    float m = POS_INF;
#pragma unroll
    for (int t = 0; t < NTILE; t++) m = fminf(m, g_tmin[gq][t]);

    const float4 a = g_sorted[aset][q];
    const float bound = fmaxf(a.w + m, 0.0f);      // best d^2 in window

    const int wlo = window_base(q >> 6);
    const int whi = wlo + NTILE * TILE;
    const float4* __restrict__ B = g_sorted[bset];

    bool unresolved = false;
    if (wlo > 0) {
        float eL  = right_edge(bucket_of(B[wlo].x));
        float dxl = fmaxf(a.x - eL, 0.0f);
        unresolved |= (dxl * dxl < bound);
    }
    if (whi < NPTS) {
        float eR  = left_edge(bucket_of(B[whi - 1].x));
        float dxr = fmaxf(eR - a.x, 0.0f);
        unresolved |= (dxr * dxr < bound);
    }

    float d = 0.0f;
    if (unresolved) {
        g_unres[atomicAdd(&g_ucnt, 1)] = gq;       // exact answer comes from fallback
    } else {
        d = sqrtf(bound);
    }

    // block sum of resolved distances
    __shared__ float sRed[RTHREADS / 32];
#pragma unroll
    for (int s = 16; s > 0; s >>= 1)
        d += __shfl_xor_sync(0xFFFFFFFFu, d, s);
    if ((threadIdx.x & 31) == 0) sRed[threadIdx.x >> 5] = d;
    __syncthreads();
    if (threadIdx.x == 0) {
        float t = 0.0f;
#pragma unroll
        for (int w = 0; w < RTHREADS / 32; w++) t += sRed[w];
        g_partial[blockIdx.x] = t;
    }
}

// ---------------- kernel 6: fallback — exact full scan for unresolved -----
__global__ void __launch_bounds__(FBTHREADS)
fallback_kernel() {
    const int cnt = g_ucnt;
    for (int i = blockIdx.x; i < cnt; i += FBBLOCKS) {
        const int gq   = g_unres[i];
        const int dir  = gq >> 14;
        const int q    = gq & (NPTS - 1);
        const float4 a = g_sorted[dir][q];
        const float amx = -2.0f * a.x, amy = -2.0f * a.y, amz = -2.0f * a.z;
        const float4* __restrict__ B = g_sorted[1 - dir];

        float m = POS_INF;
        for (int j = threadIdx.x; j < NPTS; j += FBTHREADS) {
            float4 b = B[j];
            float s = fmaf(amx, b.x, fmaf(amy, b.y, fmaf(amz, b.z, b.w)));
            m = fminf(m, s);
        }
        __shared__ float sRed[FBTHREADS / 32];
#pragma unroll
        for (int s = 16; s > 0; s >>= 1)
            m = fminf(m, __shfl_xor_sync(0xFFFFFFFFu, m, s));
        if ((threadIdx.x & 31) == 0) sRed[threadIdx.x >> 5] = m;
        __syncthreads();
        if (threadIdx.x == 0) {
            float mm = POS_INF;
#pragma unroll
            for (int w = 0; w < FBTHREADS / 32; w++) mm = fminf(mm, sRed[w]);
            atomicAdd(&g_fsum, sqrtf(fmaxf(a.w + mm, 0.0f)));
        }
        __syncthreads();
    }
}

// ---------------- kernel 7: final sum ----------------
__global__ void __launch_bounds__(RBLOCKS)
final_kernel(float* __restrict__ out) {
    float v = g_partial[threadIdx.x];
#pragma unroll
    for (int s = 16; s > 0; s >>= 1)
        v += __shfl_xor_sync(0xFFFFFFFFu, v, s);
    __shared__ float sRed[RBLOCKS / 32];
    if ((threadIdx.x & 31) == 0) sRed[threadIdx.x >> 5] = v;
    __syncthreads();
    if (threadIdx.x == 0) {
        float t = g_fsum;
#pragma unroll
        for (int w = 0; w < RBLOCKS / 32; w++) t += sRed[w];
        out[0] = t * (1.0f / (float)NPTS);
    }
}

// ---------------- launch ----------------
extern "C" void kernel_launch(void* const* d_in, const int* in_sizes, int n_in,
                              void* d_out, int out_size) {
    const float* pred = (const float*)d_in[0];
    const float* targ = (const float*)d_in[1];
    float* out = (float*)d_out;

    hist_kernel<<<HBLOCKS, HTHREADS>>>(pred, targ);
    scan_kernel<<<1, 2 * NB>>>();
    scatter_kernel<<<HBLOCKS, HTHREADS>>>(pred, targ);
    phasea_kernel<<<NGRP * NTILE, GSIZE>>>();
    resolve_kernel<<<2 * NPTS / RTHREADS, RTHREADS>>>();
    fallback_kernel<<<FBBLOCKS, FBTHREADS>>>();
    final_kernel<<<1, RBLOCKS>>>(out);
}